// round 14
// baseline (speedup 1.0000x reference)
#include <cuda_runtime.h>

// CTC forward scan split at T/2 (fwd + mirrored bwd halves on separate CTAs),
// combine = -LSE_m(F[m]+B[m]) * ln2 / T.
// THREE-STEP FUSION:
//   f'''[p] = lae4(S3+f[p], M1[s(p)]+f[p-1], M2[s(p-1),s(p)]+f[p-2],
//                  M3[s(p-2),s(p-1),s(p)]+f[p-3])
// Tables per step-triple: S3(1), M1(4: lae3), M2(16: lae3), M3(64: adds),
// staged from gmem registers into a 16-slab smem ring; ONE barrier per epoch.
// 256 threads = 8 warps, lane owns 2 positions (R11 layout). T_HALF padded
// 2048 -> 2064 with identity steps (stay=0, moves=-1e30) so K_EPOCH=24 divides.

#define T_STEPS   4096
#define T_HALF    2048
#define T_PAD     2064
#define BATCH     64
#define NFEAT     5
#define P_POS     512
#define NEG_LARGE (-1e30f)
#define K_EPOCH   24                      // steps per chunk = 8 triples
#define NITER     8                       // fused iterations per chunk
#define NCHUNK    (T_PAD / K_EPOCH)       // 86
#define NTHREADS  256
#define NWARPS    8
#define NEPOCH    (NCHUNK + NWARPS - 1)   // 93
#define GSTRIDE   88                      // S3, M1[4], M2[16], M3[64], pad
#define CSTRIDE   (NITER * GSTRIDE)       // 704 floats per chunk slab
#define NCSLAB    16
#define L2E       1.4426950408889634f
#define LN2F      0.6931471805599453f

__device__ float g_scrF[BATCH * (P_POS + 1)];
__device__ float g_scrB[BATCH * (P_POS + 1)];

__device__ __forceinline__ float ex2f(float v){ float r; asm("ex2.approx.f32 %0,%1;" : "=f"(r) : "f"(v)); return r; }
__device__ __forceinline__ float lg2f(float v){ float r; asm("lg2.approx.f32 %0,%1;" : "=f"(r) : "f"(v)); return r; }

// exact-MUFU 3-way logaddexp (staging)
__device__ __forceinline__ float lae3(float a, float b, float c) {
    float u1 = fminf(a, b);
    float u2 = fmaxf(a, b);
    float m  = fmaxf(u2, c);
    float v  = fminf(u2, c);
    float y  = 1.0f + (ex2f(u1 - m) + ex2f(v - m));
    return m + lg2f(y);
}

// exact-MUFU 4-way logaddexp: pairwise sort isolates max; 3 ex2 + 1 lg2.
__device__ __forceinline__ float lae4(float a, float b, float c, float d) {
    float u = fmaxf(a, b), l = fminf(a, b);
    float v = fmaxf(c, d), q = fminf(c, d);
    float m = fmaxf(u, v), n = fminf(u, v);
    float y = 1.0f + (ex2f(l - m) + ex2f(q - m) + ex2f(n - m));
    return m + lg2f(y);
}

__global__ void __launch_bounds__(NTHREADS, 1)
ctc_half_kernel(const float* __restrict__ x,
                const int*   __restrict__ seqs,
                const int*   __restrict__ seqlens)
{
    const bool fwdDir = (blockIdx.x & 1) == 0;
    const int  b      = blockIdx.x >> 1;
    const int  tid    = threadIdx.x;
    const int  lane   = tid & 31;
    const int  w      = tid >> 5;

    __shared__ float  cof[NCSLAB * CSTRIDE];   // coef ring
    __shared__ float4 bnd[2][NWARPS][NITER];   // (f[64w-2], f[64w-1], f[64w], -)

    const float* xb = x + b * NFEAT;
    const int    TB = BATCH * NFEAT;

    #define GTIME(s) (fwdDir ? (s) : (T_STEPS - 1 - (s)))
    // x loader with identity padding for s >= T_HALF
    #define LDX(s, f) (((s) < T_HALF) ? xb[(long)GTIME(s) * TB + (f)] * L2E \
                                      : (((f) == 4) ? 0.0f : NEG_LARGE))

    // ---- coef staging: group g = tid>>5 (8 triples/chunk), entries {j, j+32, j+64} ----
    const int g = tid >> 5;
    const int j = tid & 31;
    int   ty[3];  int fx[3], fy[3], fy2[3], fw[3];  bool val[3];
    #pragma unroll
    for (int s = 0; s < 3; ++s) {
        int e = j + 32 * s;
        val[s] = (e <= 84);
        int t_, a_ = 0, b_ = 0, b2_ = 0, c_ = 0;
        if (e == 0)       { t_ = 0; }
        else if (e <= 4)  { t_ = 1; a_ = e - 1; b_ = e - 1; c_ = e - 1; }
        else if (e <= 20) { t_ = 2; int q_ = e - 5;  a_ = q_ >> 2; b_ = q_ & 3; b2_ = a_; c_ = b_; }
        else              { t_ = 3; int q_ = e - 21; a_ = q_ >> 4; b_ = (q_ >> 2) & 3; c_ = q_ & 3; }
        ty[s] = val[s] ? t_ : -1; fx[s] = a_; fy[s] = b_; fy2[s] = b2_; fw[s] = c_;
    }

    // ---- per-lane recurrence setup: lane owns p0 = pb+1, p1 = pb+2 ----
    const int pb = (w << 6) + (lane << 1);
    const int* sp = seqs + b * P_POS;
    int sP0, sP1, sM1, sM2;                    // s(p0), s(p1), s(p0-1), s(p0-2)
    if (fwdDir) {
        sP0 = sp[pb]; sP1 = sp[pb + 1];
        sM1 = (pb >= 1) ? sp[pb - 1] : 0;
        sM2 = (pb >= 2) ? sp[pb - 2] : 0;
    } else {
        sP0 = sp[P_POS - 1 - pb]; sP1 = sp[P_POS - 2 - pb];
        sM1 = (pb >= 1) ? sp[P_POS - pb]     : 0;
        sM2 = (pb >= 2) ? sp[P_POS - pb + 1] : 0;
    }
    const int m1o0 = 1 + sP0,                 m1o1 = 1 + sP1;
    const int m2o0 = 5 + sM1 * 4 + sP0,       m2o1 = 5 + sP0 * 4 + sP1;
    const int m3o0 = 21 + sM2 * 16 + sM1 * 4 + sP0;
    const int m3o1 = 21 + sM1 * 16 + sP0 * 4 + sP1;

    const int q0 = P_POS - seqlens[b];
    float f0, f1, fz;
    if (fwdDir) {
        f0 = f1 = NEG_LARGE; fz = 0.0f;
    } else {
        f0 = (pb + 1 == q0) ? 0.f : NEG_LARGE;
        f1 = (pb + 2 == q0) ? 0.f : NEG_LARGE;
        fz = (q0 == 0) ? 0.f : NEG_LARGE;
    }

    for (int i = tid; i < 2 * NWARPS * NITER; i += NTHREADS)
        (&bnd[0][0][0])[i] = make_float4(NEG_LARGE, NEG_LARGE, NEG_LARGE, NEG_LARGE);

    // staging load+eval helpers (r[7] per slot)
    #define STG_LOAD(s, s0) do {                                            \
        int t_ = ty[s];                                                     \
        if (t_ >= 1) { r[s][0] = LDX((s0),     fx[s]);                      \
                       r[s][1] = LDX((s0) + 1, fy[s]);                      \
                       r[s][3] = LDX((s0) + 2, fw[s]); }                    \
        if (t_ == 2)   r[s][2] = LDX((s0) + 1, fy2[s]);                     \
        if (t_ >= 0 && t_ <= 2) { r[s][4] = LDX((s0),     4);               \
                                  r[s][5] = LDX((s0) + 1, 4);               \
                                  r[s][6] = LDX((s0) + 2, 4); }             \
    } while (0)

    #define STG_EVAL(s, gbase) do {                                         \
        int t_ = ty[s];                                                     \
        if (t_ == 0) (gbase)[j + 32 * (s)] = r[s][4] + r[s][5] + r[s][6];   \
        else if (t_ == 1) (gbase)[j + 32 * (s)] =                           \
            lae3(r[s][0] + r[s][5] + r[s][6],                               \
                 r[s][4] + r[s][1] + r[s][6],                               \
                 r[s][4] + r[s][5] + r[s][3]);                              \
        else if (t_ == 2) (gbase)[j + 32 * (s)] =                           \
            lae3(r[s][0] + r[s][1] + r[s][6],                               \
                 r[s][0] + r[s][5] + r[s][3],                               \
                 r[s][4] + r[s][2] + r[s][3]);                              \
        else if (t_ == 3) (gbase)[j + 32 * (s)] = r[s][0] + r[s][1] + r[s][3]; \
    } while (0)

    // ---- prologue: stage chunk 0 into slab 0 ----
    {
        float r[3][7];
        const int s0 = 3 * g;
        STG_LOAD(0, s0); STG_LOAD(1, s0); STG_LOAD(2, s0);
        float* gb = cof + g * GSTRIDE;
        STG_EVAL(0, gb); STG_EVAL(1, gb); STG_EVAL(2, gb);
    }
    __syncthreads();

    for (int e = 0; e < NEPOCH; ++e) {
        // ---- issue LDGs for chunk e+1 (hidden under the 8 fused iters) ----
        float r[3][7];
        const bool pf = (e + 1) < NCHUNK;
        if (pf) {
            const int s0 = (e + 1) * K_EPOCH + 3 * g;
            STG_LOAD(0, s0); STG_LOAD(1, s0); STG_LOAD(2, s0);
        }

        const int  c     = e - w;
        const bool valid = (c >= 0) && (c < NCHUNK);

        if (valid) {
            const float*  cs = cof + (c & (NCSLAB - 1)) * CSTRIDE;
            const float4* bR = bnd[(e & 1) ^ 1][(w > 0) ? (w - 1) : 0];
            float4*       bW = &bnd[e & 1][w][0];

            #pragma unroll
            for (int k = 0; k < NITER; ++k) {
                const float* gb = cs + k * GSTRIDE;
                float S3  = gb[0];
                float M1a = gb[m1o0], M1b = gb[m1o1];
                float M2a = gb[m2o0], M2b = gb[m2o1];
                float M3a = gb[m3o0], M3b = gb[m3o1];
                float4 bv = bR[k];

                float La1 = __shfl_up_sync(0xffffffffu, f1, 1);   // f[pb]
                float La0 = __shfl_up_sync(0xffffffffu, f0, 1);   // f[pb-1]
                float Lb1 = __shfl_up_sync(0xffffffffu, f1, 2);   // f[pb-2]
                if (lane == 31) bW[k] = make_float4(La1, f0, f1, 0.f);
                if (lane == 0) {
                    La1 = w ? bv.z : fz;
                    La0 = w ? bv.y : NEG_LARGE;
                    Lb1 = w ? bv.x : NEG_LARGE;
                } else if (lane == 1) {
                    Lb1 = w ? bv.z : fz;
                }

                float A0 = S3 + f0, B0 = M1a + La1, C0 = M2a + La0, D0 = M3a + Lb1;
                float A1 = S3 + f1, B1 = M1b + f0,  C1 = M2b + La1, D1 = M3b + La0;
                if (w == 0) fz += S3;

                f0 = lae4(A0, B0, C0, D0);
                f1 = lae4(A1, B1, C1, D1);
            }
        }

        // ---- compute + commit coefs for chunk e+1 ----
        if (pf) {
            float* gb = cof + ((e + 1) & (NCSLAB - 1)) * CSTRIDE + g * GSTRIDE;
            STG_EVAL(0, gb); STG_EVAL(1, gb); STG_EVAL(2, gb);
        }
        __syncthreads();
    }

    // ---- epilogue: write half-result. fwd: index = position; bwd: m = P - q. ----
    float* scr = fwdDir ? (g_scrF + b * (P_POS + 1)) : (g_scrB + b * (P_POS + 1));
    if (fwdDir) {
        scr[pb + 1] = f0; scr[pb + 2] = f1;
        if (tid == 0) scr[0] = fz;
    } else {
        scr[P_POS - (pb + 1)] = f0;
        scr[P_POS - (pb + 2)] = f1;
        if (tid == 0) scr[P_POS] = fz;
    }
}

__global__ void __launch_bounds__(128)
ctc_combine_kernel(float* __restrict__ out)
{
    const int b    = blockIdx.x;
    const int tid  = threadIdx.x;
    const int lane = tid & 31;
    const int w    = tid >> 5;
    __shared__ float red[4];

    const float* F = g_scrF + b * (P_POS + 1);
    const float* B = g_scrB + b * (P_POS + 1);

    float vm = -3e38f;
    float v[5];
    int   nv = 0;
    for (int p = tid; p <= P_POS; p += 128) {
        float t = F[p] + B[p];
        v[nv++] = t;
        vm = fmaxf(vm, t);
    }
    #pragma unroll
    for (int off = 16; off; off >>= 1)
        vm = fmaxf(vm, __shfl_xor_sync(0xffffffffu, vm, off));
    if (lane == 0) red[w] = vm;
    __syncthreads();
    vm = fmaxf(fmaxf(red[0], red[1]), fmaxf(red[2], red[3]));

    float s = 0.f;
    for (int i = 0; i < nv; ++i) s += ex2f(v[i] - vm);
    #pragma unroll
    for (int off = 16; off; off >>= 1)
        s += __shfl_xor_sync(0xffffffffu, s, off);
    __syncthreads();
    if (lane == 0) red[w] = s;
    __syncthreads();
    if (tid == 0) {
        float st = red[0] + red[1] + red[2] + red[3];
        float lse = vm + lg2f(st);
        out[b] = -lse * (LN2F / (float)T_STEPS);
    }
}

extern "C" void kernel_launch(void* const* d_in, const int* in_sizes, int n_in,
                              void* d_out, int out_size)
{
    const float* x       = (const float*)d_in[0];
    const int*   seqs    = (const int*)  d_in[1];
    const int*   seqlens = (const int*)  d_in[2];
    float*       out     = (float*)      d_out;

    ctc_half_kernel<<<2 * BATCH, NTHREADS>>>(x, seqs, seqlens);
    ctc_combine_kernel<<<BATCH, 128>>>(out);
}

// round 15
// speedup vs baseline: 2.3516x; 2.3516x over previous
#include <cuda_runtime.h>

// CTC forward scan split at T/2 (fwd + mirrored bwd halves on separate CTAs).
// R11 core: TWO-STEP FUSION, f''[p] = lae3(S2+f[p], M1[sj(p)]+f[p-1],
// M2[sj(p-1),sj(p)]+f[p-2]); coefs (S2,M1[4],M2[16]) per step-pair in a
// 16-slab smem ring sourced from gmem registers; ONE barrier per epoch;
// 256 threads = 8 warps, lane owns 2 positions; exact 2-MUFU lae3.
// NEW vs R11: combine fused into the bwd CTA. bwd keeps B in smem; fwd CTA
// publishes F via flag (release/acquire with atomics+fences); bwd spins,
// reduces -LSE(F+B)*ln2/T, writes out[b], resets the flag for graph replays.

#define T_STEPS   4096
#define T_HALF    2048
#define BATCH     64
#define NFEAT     5
#define P_POS     512
#define NEG_LARGE (-1e30f)
#define K_EPOCH   32
#define NITER     16                      // fused iterations per chunk
#define NCHUNK    (T_HALF / K_EPOCH)      // 64
#define NTHREADS  256
#define NWARPS    8
#define NEPOCH    (NCHUNK + NWARPS - 1)   // 71
#define GSTRIDE   24                      // S2, M1[4], M2[16], pad
#define CSTRIDE   (NITER * GSTRIDE)       // 384 floats per chunk slab
#define NCSLAB    16
#define L2E       1.4426950408889634f
#define LN2F      0.6931471805599453f

__device__ float g_scrF[BATCH * (P_POS + 1)];
__device__ int   g_flagF[BATCH];          // 0 = empty, 1 = F ready (reset by consumer)

__device__ __forceinline__ float ex2f(float v){ float r; asm("ex2.approx.f32 %0,%1;" : "=f"(r) : "f"(v)); return r; }
__device__ __forceinline__ float lg2f(float v){ float r; asm("lg2.approx.f32 %0,%1;" : "=f"(r) : "f"(v)); return r; }

// accurate 2-MUFU logaddexp (log2 domain) — staging only
__device__ __forceinline__ float lae2(float a, float b) {
    float m = fmaxf(a, b);
    float d = -fabsf(a - b);
    return m + lg2f(1.0f + ex2f(d));
}

// 3-way logaddexp (log2 domain): max term's ex2 (==1) skipped via sort. Exact MUFU.
__device__ __forceinline__ float lae3(float a, float b, float c) {
    float u1 = fminf(a, b);
    float u2 = fmaxf(a, b);
    float m  = fmaxf(u2, c);
    float v  = fminf(u2, c);
    float y  = 1.0f + (ex2f(u1 - m) + ex2f(v - m));
    return m + lg2f(y);
}

__global__ void __launch_bounds__(NTHREADS, 1)
ctc_half_kernel(const float* __restrict__ x,
                const int*   __restrict__ seqs,
                const int*   __restrict__ seqlens,
                float*       __restrict__ out)
{
    const bool fwdDir = (blockIdx.x & 1) == 0;
    const int  b      = blockIdx.x >> 1;
    const int  tid    = threadIdx.x;
    const int  lane   = tid & 31;
    const int  w      = tid >> 5;

    __shared__ float  cof[NCSLAB * CSTRIDE];   // fused coefs per chunk (ring)
    __shared__ float2 bnd[2][NWARPS][NITER];   // lane31 (f0,f1) entering iter k
    __shared__ float  Bsh[P_POS + 1];          // bwd CTA: B vector for combine
    __shared__ float  red[NWARPS];             // combine reduction scratch

    const float* xb = x + b * NFEAT;           // x[t*B*F + b*F + f]
    const int    TB = BATCH * NFEAT;

    // ---- per-thread coef staging assignment: group g, slot j ----
    // out0 -> gb[j]:  j==0: S2 | j in 1..4: M1[j-1] | j in 5..15: M2[j-5]
    // out1 -> gb[16+j] (j<=4 only): M2[11+j]
    const int g  = tid >> 4;
    const int j  = tid & 15;
    const bool hasOut1 = (j <= 4);
    int fa0, fa1; bool isM1 = false;
    if (j == 0)      { fa0 = 4; fa1 = 4; }
    else if (j <= 4) { fa0 = j - 1; fa1 = j - 1; isM1 = true; }
    else             { int ei = j - 5; fa0 = ei >> 2; fa1 = ei & 3; }
    const int fb0 = (11 + j) >> 2;
    const int fb1 = (11 + j) & 3;

    // ---- per-lane recurrence setup: lane owns positions pb+1, pb+2 ----
    const int pb = (w << 6) + (lane << 1);
    const int* sp = seqs + b * P_POS;
    int si0, si1, idxA;                        // sj(p0), sj(p1), sj(p0-1)
    if (fwdDir) {
        si0  = sp[pb];
        si1  = sp[pb + 1];
        idxA = (pb == 0) ? 0 : sp[pb - 1];
    } else {
        si0  = sp[P_POS - 1 - pb];
        si1  = sp[P_POS - 2 - pb];
        idxA = (pb == 0) ? 0 : sp[P_POS - pb];
    }
    const int m1o0 = 1 + si0;
    const int m1o1 = 1 + si1;
    const int m2o0 = 5 + idxA * 4 + si0;
    const int m2o1 = 5 + si0  * 4 + si1;

    const int q0 = P_POS - seqlens[b];
    float f0, f1, fz;
    if (fwdDir) {
        f0 = f1 = NEG_LARGE; fz = 0.0f;
    } else {
        f0 = (pb + 1 == q0) ? 0.f : NEG_LARGE;
        f1 = (pb + 2 == q0) ? 0.f : NEG_LARGE;
        fz = (q0 == 0) ? 0.f : NEG_LARGE;
    }

    for (int i = tid; i < 2 * NWARPS * NITER; i += NTHREADS)
        (&bnd[0][0][0])[i] = make_float2(NEG_LARGE, NEG_LARGE);

    #define GTIME(s) (fwdDir ? (s) : (T_STEPS - 1 - (s)))

    // ---- prologue: stage coefs for chunk 0 into slab 0 ----
    {
        const int s0 = 2 * g, s1 = 2 * g + 1;
        const long o0 = (long)GTIME(s0) * TB, o1 = (long)GTIME(s1) * TB;
        float a0 = xb[o0 + fa0] * L2E;
        float a1 = xb[o1 + fa1] * L2E;
        float st0 = 0.f, st1 = 0.f, b0v = 0.f, b1v = 0.f;
        if (isM1) { st0 = xb[o0 + 4] * L2E; st1 = xb[o1 + 4] * L2E; }
        if (hasOut1) { b0v = xb[o0 + fb0] * L2E; b1v = xb[o1 + fb1] * L2E; }
        float* gb = cof + g * GSTRIDE;
        gb[j] = isM1 ? lae2(a0 + st1, st0 + a1) : (a0 + a1);
        if (hasOut1) gb[16 + j] = b0v + b1v;
    }
    __syncthreads();

    for (int e = 0; e < NEPOCH; ++e) {
        // ---- issue LDGs for chunk e+1 coef inputs (hidden under compute) ----
        float a0 = 0.f, a1 = 0.f, st0 = 0.f, st1 = 0.f, b0v = 0.f, b1v = 0.f;
        const bool pf = (e + 1) < NCHUNK;
        if (pf) {
            const int s0 = (e + 1) * K_EPOCH + 2 * g, s1 = s0 + 1;
            const long o0 = (long)GTIME(s0) * TB, o1 = (long)GTIME(s1) * TB;
            a0 = xb[o0 + fa0] * L2E;
            a1 = xb[o1 + fa1] * L2E;
            if (isM1) { st0 = xb[o0 + 4] * L2E; st1 = xb[o1 + 4] * L2E; }
            if (hasOut1) { b0v = xb[o0 + fb0] * L2E; b1v = xb[o1 + fb1] * L2E; }
        }

        const int  c     = e - w;
        const bool valid = (c >= 0) && (c < NCHUNK);

        if (valid) {
            const float*  cs = cof + (c & (NCSLAB - 1)) * CSTRIDE;
            const float2* bR = bnd[(e & 1) ^ 1][(w > 0) ? (w - 1) : 0];
            float2*       bW = &bnd[e & 1][w][0];

            #pragma unroll
            for (int k = 0; k < NITER; ++k) {
                const float* gb  = cs + k * GSTRIDE;
                float S2  = gb[0];
                float M1a = gb[m1o0];
                float M1b = gb[m1o1];
                float M2a = gb[m2o0];
                float M2b = gb[m2o1];
                float2 bv = bR[k];

                float Lf0 = __shfl_up_sync(0xffffffffu, f0, 1);
                float Lf1 = __shfl_up_sync(0xffffffffu, f1, 1);
                if (lane == 0) {
                    Lf0 = (w == 0) ? NEG_LARGE : bv.x;
                    Lf1 = (w == 0) ? fz        : bv.y;
                }
                if (lane == 31) bW[k] = make_float2(f0, f1);

                float A0 = S2 + f0;
                float B0 = M1a + Lf1;
                float C0 = M2a + Lf0;
                float A1 = S2 + f1;
                float B1 = M1b + f0;     // old f0
                float C1 = M2b + Lf1;
                if (w == 0) fz += S2;

                f0 = lae3(A0, B0, C0);
                f1 = lae3(A1, B1, C1);
            }
        }

        // ---- compute + commit coefs for chunk e+1 ----
        if (pf) {
            float* gb = cof + ((e + 1) & (NCSLAB - 1)) * CSTRIDE + g * GSTRIDE;
            gb[j] = isM1 ? lae2(a0 + st1, st0 + a1) : (a0 + a1);
            if (hasOut1) gb[16 + j] = b0v + b1v;
        }
        __syncthreads();
    }

    // ---- epilogue ----
    if (fwdDir) {
        // publish F to gmem, then release flag
        float* scr = g_scrF + b * (P_POS + 1);
        scr[pb + 1] = f0; scr[pb + 2] = f1;
        if (tid == 0) scr[0] = fz;
        __threadfence();
        __syncthreads();
        if (tid == 0) atomicExch(&g_flagF[b], 1);
    } else {
        // keep B in smem (index m = P - q), acquire F, combine, write out[b]
        Bsh[P_POS - (pb + 1)] = f0;
        Bsh[P_POS - (pb + 2)] = f1;
        if (tid == 0) Bsh[P_POS] = fz;     // q=0 -> m=P
        __syncthreads();
        if (tid == 0) { while (atomicAdd(&g_flagF[b], 0) == 0) { } }
        __syncthreads();
        __threadfence();

        const float* F = g_scrF + b * (P_POS + 1);
        float vm = -3e38f;
        float v[3];
        int   nv = 0;
        #pragma unroll
        for (int p = tid; p <= P_POS; p += NTHREADS) {
            float t = __ldcg(F + p) + Bsh[p];
            v[nv++] = t;
            vm = fmaxf(vm, t);
        }
        #pragma unroll
        for (int off = 16; off; off >>= 1)
            vm = fmaxf(vm, __shfl_xor_sync(0xffffffffu, vm, off));
        if (lane == 0) red[w] = vm;
        __syncthreads();
        vm = red[0];
        #pragma unroll
        for (int i = 1; i < NWARPS; ++i) vm = fmaxf(vm, red[i]);

        float s = 0.f;
        for (int i = 0; i < nv; ++i) s += ex2f(v[i] - vm);
        #pragma unroll
        for (int off = 16; off; off >>= 1)
            s += __shfl_xor_sync(0xffffffffu, s, off);
        __syncthreads();
        if (lane == 0) red[w] = s;
        __syncthreads();
        if (tid == 0) {
            float st = 0.f;
            #pragma unroll
            for (int i = 0; i < NWARPS; ++i) st += red[i];
            out[b] = -(vm + lg2f(st)) * (LN2F / (float)T_STEPS);
            atomicExch(&g_flagF[b], 0);    // reset for next graph replay
        }
    }
}

extern "C" void kernel_launch(void* const* d_in, const int* in_sizes, int n_in,
                              void* d_out, int out_size)
{
    const float* x       = (const float*)d_in[0];
    const int*   seqs    = (const int*)  d_in[1];
    const int*   seqlens = (const int*)  d_in[2];
    float*       out     = (float*)      d_out;

    ctc_half_kernel<<<2 * BATCH, NTHREADS>>>(x, seqs, seqlens, out);
}